// round 6
// baseline (speedup 1.0000x reference)
#include <cuda_runtime.h>

// Problem constants
#define TOK_TOTAL 4096      // B_SZ * L = 2 * 2048
#define Dm        1024
#define TPB       256
#define TOKS      8                       // tokens per block
#define NBLK      (TOK_TOTAL / TOKS)      // 512 blocks
#define OUT_F4_PER_TOK 8196               // (2*1024+1)*16/4
#define PROJ_STRIDE_F4 9                  // padded proj row: 9 float4 = 36 floats

__device__ __forceinline__ float softplus_f(float v) {
    // matches jax.nn.softplus = max(x,0) + log1p(exp(-|x|))
    return fmaxf(v, 0.0f) + log1pf(__expf(-fabsf(v)));
}

__global__ void __launch_bounds__(TPB, 4) ssm_fused_kernel(
    const float* __restrict__ x,
    const float* __restrict__ Wb,
    const float* __restrict__ Wc,
    const float* __restrict__ Wd,
    const float* __restrict__ A,
    const float* __restrict__ dp,
    float* __restrict__ out)
{
    // ALL shared arrays are float4-typed: 16B alignment is guaranteed by the
    // type system, never by a reinterpret-cast of a float symbol.
    __shared__ float4 sx[TOKS * Dm / 4];            // 32 KB: 8 x rows
    __shared__ float4 s_dp4[Dm / 4];                // 4 KB: delta_param
    __shared__ float4 proj4[TOKS * PROJ_STRIDE_F4]; // [8][9] f4 = [8][36] floats

    float* projf = (float*)proj4;                   // scalar view (writes)
    const float* s_dp = (const float*)s_dp4;
    const float* sxf  = (const float*)sx;

    const int tid  = threadIdx.x;
    const int bt   = blockIdx.x;
    const int lane = tid & 31;
    const int w    = tid >> 5;

    // ---- Stage 8 contiguous x rows (32 KB) + delta_param ----
    const float4* x4 = (const float4*)x + (size_t)bt * (TOKS * Dm / 4);
    #pragma unroll
    for (int i = 0; i < (TOKS * Dm / 4) / TPB; ++i)   // 8 iters
        sx[tid + i * TPB] = __ldg(x4 + tid + i * TPB);
    s_dp4[tid & 255] = __ldg((const float4*)dp + (tid & 255));
    __syncthreads();

    // ---- Projections: 33 dot products x 8 tokens. Warp w owns cols {w, w+8,...} ----
    for (int c = w; c < 33; c += 8) {
        const float* Wrow = (c < 16) ? (Wb + c * Dm)
                          : (c < 32) ? (Wc + (c - 16) * Dm)
                          : Wd;
        const float4* W4 = (const float4*)Wrow;
        float acc[TOKS];
        #pragma unroll
        for (int t = 0; t < TOKS; ++t) acc[t] = 0.0f;
        #pragma unroll
        for (int k = 0; k < 8; ++k) {
            float4 wv = __ldg(W4 + lane + 32 * k);
            #pragma unroll
            for (int t = 0; t < TOKS; ++t) {
                float4 xv = sx[t * 256 + lane + 32 * k];
                acc[t] = fmaf(xv.x, wv.x, acc[t]);
                acc[t] = fmaf(xv.y, wv.y, acc[t]);
                acc[t] = fmaf(xv.z, wv.z, acc[t]);
                acc[t] = fmaf(xv.w, wv.w, acc[t]);
            }
        }
        #pragma unroll
        for (int t = 0; t < TOKS; ++t) {
            float a = acc[t];
            a += __shfl_xor_sync(0xffffffffu, a, 16);
            a += __shfl_xor_sync(0xffffffffu, a, 8);
            a += __shfl_xor_sync(0xffffffffu, a, 4);
            a += __shfl_xor_sync(0xffffffffu, a, 2);
            a += __shfl_xor_sync(0xffffffffu, a, 1);
            if (lane == 0) projf[t * (PROJ_STRIDE_F4 * 4) + c] = a;
        }
    }
    __syncthreads();

    const float4* A4   = (const float4*)A;
    float4*       out4 = (float4*)out;

    // ---- Per-token expansion: pure streaming stores, no further syncs ----
    for (int tt = 0; tt < TOKS; ++tt) {
        const int token = bt * TOKS + tt;
        float4* ob = out4 + (size_t)token * OUT_F4_PER_TOK;
        const float4* pjB  = proj4 + tt * PROJ_STRIDE_F4;        // B as 4 aligned f4
        const float*  pjf  = (const float*)pjB;
        const float   sdel = pjf[32];

        #pragma unroll 4
        for (int j = 0; j < 16; ++j) {
            const int f  = tid + j * TPB;
            const int d  = f >> 2;
            const int nq = f & 3;

            const float Delta = softplus_f(sdel + s_dp[d]);   // quad-broadcast LDS
            const float xd    = sxf[tt * Dm + d];
            const float4 a    = __ldg(A4 + f);                // L1-resident after 1st token
            const float4 Bq   = pjB[nq];                      // aligned LDS.128 broadcast

            float4 ab;
            ab.x = __expf(Delta * a.x);
            ab.y = __expf(Delta * a.y);
            ab.z = __expf(Delta * a.z);
            ab.w = __expf(Delta * a.w);

            // deltaB_x = (A_bar-1)/dA * Delta*B*x = (A_bar-1) * B * x / A
            float4 o2;
            o2.x = __fdividef((ab.x - 1.0f) * (Bq.x * xd), a.x);
            o2.y = __fdividef((ab.y - 1.0f) * (Bq.y * xd), a.y);
            o2.z = __fdividef((ab.z - 1.0f) * (Bq.z * xd), a.z);
            o2.w = __fdividef((ab.w - 1.0f) * (Bq.w * xd), a.w);

            __stcs(ob + f, ab);            // A_bar plane  [0, 4096)
            __stcs(ob + 4096 + f, o2);     // deltaB_x     [4096, 8192)
        }

        // C row: 16 floats at f4 offset 8192 (pjB[4..7] = C, aligned reads)
        if (tid < 4) {
            __stcs(ob + 8192 + tid, pjB[4 + tid]);
        }
    }
}

extern "C" void kernel_launch(void* const* d_in, const int* in_sizes, int n_in,
                              void* d_out, int out_size)
{
    const float* x  = (const float*)d_in[0];
    const float* Wb = (const float*)d_in[1];
    const float* Wc = (const float*)d_in[2];
    const float* Wd = (const float*)d_in[3];
    const float* A  = (const float*)d_in[4];
    const float* dp = (const float*)d_in[5];

    ssm_fused_kernel<<<NBLK, TPB>>>(x, Wb, Wc, Wd, A, dp, (float*)d_out);
}

// round 7
// speedup vs baseline: 1.0825x; 1.0825x over previous
#include <cuda_runtime.h>

// Problem constants
#define TOK_TOTAL 4096      // B_SZ * L = 2 * 2048
#define Dm        1024
#define TPB       256
#define TOKS      8                       // tokens per proj block
#define NBLK_PROJ (TOK_TOTAL / TOKS)      // 512
#define OUT_F4_PER_TOK 8196               // (2*1024+1)*16/4
#define PROJ_F4   9                       // proj row: 9 float4 = 36 floats

// Projection scratch: [4096][9] float4 = [4096][36] floats.
// Row: B = f4[0..3], C = f4[4..7], s_delta = f4[8].x
__device__ float4 g_proj4[TOK_TOTAL * PROJ_F4];

__device__ __forceinline__ float softplus_f(float v) {
    // matches jax.nn.softplus = max(x,0) + log1p(exp(-|x|))
    return fmaxf(v, 0.0f) + log1pf(__expf(-fabsf(v)));
}

// ---------------------------------------------------------------------------
// Kernel 1: projections (R6-proven structure). 8 tokens/block.
// ---------------------------------------------------------------------------
__global__ void __launch_bounds__(TPB) ssm_proj_kernel(
    const float* __restrict__ x,
    const float* __restrict__ Wb,
    const float* __restrict__ Wc,
    const float* __restrict__ Wd)
{
    __shared__ float4 sx[TOKS * Dm / 4];   // 32 KB

    float* gp = (float*)g_proj4;

    const int tid  = threadIdx.x;
    const int bt   = blockIdx.x;
    const int lane = tid & 31;
    const int w    = tid >> 5;

    const float4* x4 = (const float4*)x + (size_t)bt * (TOKS * Dm / 4);
    #pragma unroll
    for (int i = 0; i < (TOKS * Dm / 4) / TPB; ++i)    // 8 iters
        sx[tid + i * TPB] = __ldg(x4 + tid + i * TPB);
    __syncthreads();

    for (int c = w; c < 33; c += 8) {
        const float* Wrow = (c < 16) ? (Wb + c * Dm)
                          : (c < 32) ? (Wc + (c - 16) * Dm)
                          : Wd;
        const float4* W4 = (const float4*)Wrow;
        float acc[TOKS];
        #pragma unroll
        for (int t = 0; t < TOKS; ++t) acc[t] = 0.0f;
        #pragma unroll
        for (int k = 0; k < 8; ++k) {
            float4 wv = __ldg(W4 + lane + 32 * k);
            #pragma unroll
            for (int t = 0; t < TOKS; ++t) {
                float4 xv = sx[t * 256 + lane + 32 * k];
                acc[t] = fmaf(xv.x, wv.x, acc[t]);
                acc[t] = fmaf(xv.y, wv.y, acc[t]);
                acc[t] = fmaf(xv.z, wv.z, acc[t]);
                acc[t] = fmaf(xv.w, wv.w, acc[t]);
            }
        }
        #pragma unroll
        for (int t = 0; t < TOKS; ++t) {
            float a = acc[t];
            a += __shfl_xor_sync(0xffffffffu, a, 16);
            a += __shfl_xor_sync(0xffffffffu, a, 8);
            a += __shfl_xor_sync(0xffffffffu, a, 4);
            a += __shfl_xor_sync(0xffffffffu, a, 2);
            a += __shfl_xor_sync(0xffffffffu, a, 1);
            if (lane == 0) gp[(size_t)(bt * TOKS + t) * 36 + c] = a;
        }
    }
}

// ---------------------------------------------------------------------------
// Kernel 2: expansion. One token per block; ~95% pure streaming stores.
// ---------------------------------------------------------------------------
__global__ void __launch_bounds__(TPB, 5) ssm_expand_kernel(
    const float* __restrict__ x,
    const float* __restrict__ A,
    const float* __restrict__ dp,
    float* __restrict__ out)
{
    __shared__ float2 s_dx[Dm];     // (Delta, x) per d — 8 KB, one LDS.64 in loop
    __shared__ float4 s_pj[PROJ_F4];

    const int tid   = threadIdx.x;
    const int token = blockIdx.x;
    const float* gp = (const float*)g_proj4;

    // ---- Stage: softplus once per d, pack (Delta, x); proj row broadcast ----
    {
        const float sdel = __ldg(gp + (size_t)token * 36 + 32);  // L2-hit broadcast
        const float4 xv  = __ldg((const float4*)x + (size_t)token * (Dm / 4) + tid);
        const float4 dpv = __ldg((const float4*)dp + tid);
        const int d0 = tid * 4;
        s_dx[d0 + 0] = make_float2(softplus_f(sdel + dpv.x), xv.x);
        s_dx[d0 + 1] = make_float2(softplus_f(sdel + dpv.y), xv.y);
        s_dx[d0 + 2] = make_float2(softplus_f(sdel + dpv.z), xv.z);
        s_dx[d0 + 3] = make_float2(softplus_f(sdel + dpv.w), xv.w);
        if (tid < PROJ_F4) s_pj[tid] = __ldg(g_proj4 + (size_t)token * PROJ_F4 + tid);
    }
    __syncthreads();

    const float4 Bq = s_pj[tid & 3];            // per-thread invariant B quad
    const float4* A4 = (const float4*)A;
    float4* ob = (float4*)out + (size_t)token * OUT_F4_PER_TOK;

    #pragma unroll 4
    for (int j = 0; j < 16; ++j) {
        const int f = tid + j * TPB;
        const int d = (tid >> 2) + j * 64;

        const float2 dx = s_dx[d];              // Delta, x — one LDS.64
        const float4 a  = __ldg(A4 + f);        // L1/L2-resident

        float4 ab;
        ab.x = __expf(dx.x * a.x);
        ab.y = __expf(dx.x * a.y);
        ab.z = __expf(dx.x * a.z);
        ab.w = __expf(dx.x * a.w);

        // deltaB_x = (A_bar-1)/dA * Delta*B*x = (A_bar-1) * (B*x) / A
        float4 o2;
        o2.x = __fdividef((ab.x - 1.0f) * (Bq.x * dx.y), a.x);
        o2.y = __fdividef((ab.y - 1.0f) * (Bq.y * dx.y), a.y);
        o2.z = __fdividef((ab.z - 1.0f) * (Bq.z * dx.y), a.z);
        o2.w = __fdividef((ab.w - 1.0f) * (Bq.w * dx.y), a.w);

        __stcs(ob + f, ab);            // A_bar plane  [0, 4096)
        __stcs(ob + 4096 + f, o2);     // deltaB_x     [4096, 8192)
    }

    // C row: 16 floats at f4 offset 8192 (s_pj[4..7])
    if (tid < 4) {
        __stcs(ob + 8192 + tid, s_pj[4 + tid]);
    }
}

extern "C" void kernel_launch(void* const* d_in, const int* in_sizes, int n_in,
                              void* d_out, int out_size)
{
    const float* x  = (const float*)d_in[0];
    const float* Wb = (const float*)d_in[1];
    const float* Wc = (const float*)d_in[2];
    const float* Wd = (const float*)d_in[3];
    const float* A  = (const float*)d_in[4];
    const float* dp = (const float*)d_in[5];

    ssm_proj_kernel<<<NBLK_PROJ, TPB>>>(x, Wb, Wc, Wd);
    ssm_expand_kernel<<<TOK_TOTAL, TPB>>>(x, A, dp, (float*)d_out);
}

// round 10
// speedup vs baseline: 1.1758x; 1.0863x over previous
#include <cuda_runtime.h>

// Problem constants
#define TOK_TOTAL 4096      // B_SZ * L = 2 * 2048
#define Dm        1024
#define TPB       256
#define TOKS      2                       // tokens per block
#define NBLK      (TOK_TOTAL / TOKS)      // 2048 blocks
#define OUT_F4_PER_TOK 8196               // (2*1024+1)*16/4

__device__ __forceinline__ float softplus_f(float v) {
    // matches jax.nn.softplus = max(x,0) + log1p(exp(-|x|))
    return fmaxf(v, 0.0f) + log1pf(__expf(-fabsf(v)));
}

__global__ void __launch_bounds__(TPB, 5) ssm_fused_kernel(
    const float* __restrict__ x,
    const float* __restrict__ Wb,
    const float* __restrict__ Wc,
    const float* __restrict__ Wd,
    const float* __restrict__ A,
    const float* __restrict__ dp,
    float* __restrict__ out)
{
    // All shared arrays vector-typed: alignment guaranteed by the type system.
    __shared__ float4 s_x[TOKS][Dm / 4];   // 8 KB: 2 x rows
    __shared__ float2 s_dx[TOKS][Dm];      // 16 KB: (Delta, x) per (token, d)
    __shared__ float4 s_pj4[TOKS][9];      // [2][36] floats: B(0..15) C(16..31) sdel(32)

    float* s_pjf = (float*)s_pj4;          // row t at float offset t*36 (144 B, aligned)

    const int tid  = threadIdx.x;
    const int bt   = blockIdx.x;
    const int lane = tid & 31;
    const int w    = tid >> 5;

    const float4* A4 = (const float4*)A;

    // ---- Warm A's first lines into L1/L2 overlapped with the FMA prologue ----
    float4 a_pre = __ldg(A4 + tid);

    // ---- Stage 2 x rows (8 KB) ----
    const float4* x4 = (const float4*)x + (size_t)bt * (TOKS * Dm / 4);
    #pragma unroll
    for (int t = 0; t < TOKS; ++t)
        s_x[t][tid] = __ldg(x4 + t * 256 + tid);
    const float4 dpv = __ldg((const float4*)dp + tid);
    __syncthreads();

    // ---- Projections: 33 dots x 2 tokens. Warp w owns cols {w, w+8, ...} ----
    for (int c = w; c < 33; c += 8) {
        const float* Wrow = (c < 16) ? (Wb + c * Dm)
                          : (c < 32) ? (Wc + (c - 16) * Dm)
                          : Wd;
        const float4* W4 = (const float4*)Wrow;
        float acc0 = 0.0f, acc1 = 0.0f;
        #pragma unroll
        for (int k = 0; k < 8; ++k) {
            float4 wv = __ldg(W4 + lane + 32 * k);   // L1-resident across blocks
            float4 x0 = s_x[0][lane + 32 * k];
            float4 x1 = s_x[1][lane + 32 * k];
            acc0 = fmaf(x0.x, wv.x, acc0); acc1 = fmaf(x1.x, wv.x, acc1);
            acc0 = fmaf(x0.y, wv.y, acc0); acc1 = fmaf(x1.y, wv.y, acc1);
            acc0 = fmaf(x0.z, wv.z, acc0); acc1 = fmaf(x1.z, wv.z, acc1);
            acc0 = fmaf(x0.w, wv.w, acc0); acc1 = fmaf(x1.w, wv.w, acc1);
        }
        #pragma unroll
        for (int s = 16; s >= 1; s >>= 1) {
            acc0 += __shfl_xor_sync(0xffffffffu, acc0, s);
            acc1 += __shfl_xor_sync(0xffffffffu, acc1, s);
        }
        if (lane == 0) {
            s_pjf[0 * 36 + c] = acc0;
            s_pjf[1 * 36 + c] = acc1;
        }
    }
    __syncthreads();

    // ---- Softplus once per (token, d); pack (Delta, x) ----
    {
        const int d0 = tid * 4;
        #pragma unroll
        for (int t = 0; t < TOKS; ++t) {
            const float sdel = s_pjf[t * 36 + 32];
            const float4 xv  = s_x[t][tid];
            s_dx[t][d0 + 0] = make_float2(softplus_f(sdel + dpv.x), xv.x);
            s_dx[t][d0 + 1] = make_float2(softplus_f(sdel + dpv.y), xv.y);
            s_dx[t][d0 + 2] = make_float2(softplus_f(sdel + dpv.z), xv.z);
            s_dx[t][d0 + 3] = make_float2(softplus_f(sdel + dpv.w), xv.w);
        }
    }
    __syncthreads();

    float4* out4 = (float4*)out;

    // ---- Per-token expansion: pure streaming stores ----
    #pragma unroll
    for (int tt = 0; tt < TOKS; ++tt) {
        const int token = bt * TOKS + tt;
        float4* ob = out4 + (size_t)token * OUT_F4_PER_TOK;
        const float4 Bq = s_pj4[tt][tid & 3];     // per-thread invariant B quad

        #pragma unroll 4
        for (int j = 0; j < 16; ++j) {
            const int f = tid + j * TPB;
            const int d = (tid >> 2) + j * 64;

            const float2 dx = s_dx[tt][d];        // Delta, x — one LDS.64
            const float4 a  = (tt == 0 && j == 0) ? a_pre : __ldg(A4 + f);

            float4 ab;
            ab.x = __expf(dx.x * a.x);
            ab.y = __expf(dx.x * a.y);
            ab.z = __expf(dx.x * a.z);
            ab.w = __expf(dx.x * a.w);

            // deltaB_x = (A_bar-1)/dA * Delta*B*x = (A_bar-1) * (B*x) / A
            float4 o2;
            o2.x = __fdividef((ab.x - 1.0f) * (Bq.x * dx.y), a.x);
            o2.y = __fdividef((ab.y - 1.0f) * (Bq.y * dx.y), a.y);
            o2.z = __fdividef((ab.z - 1.0f) * (Bq.z * dx.y), a.z);
            o2.w = __fdividef((ab.w - 1.0f) * (Bq.w * dx.y), a.w);

            __stcs(ob + f, ab);            // A_bar plane  [0, 4096)
            __stcs(ob + 4096 + f, o2);     // deltaB_x     [4096, 8192)
        }

        // C row: 16 floats at f4 offset 8192 (s_pj4[tt][4..7])
        if (tid < 4) {
            __stcs(ob + 8192 + tid, s_pj4[tt][4 + tid]);
        }
    }
}

extern "C" void kernel_launch(void* const* d_in, const int* in_sizes, int n_in,
                              void* d_out, int out_size)
{
    const float* x  = (const float*)d_in[0];
    const float* Wb = (const float*)d_in[1];
    const float* Wc = (const float*)d_in[2];
    const float* Wd = (const float*)d_in[3];
    const float* A  = (const float*)d_in[4];
    const float* dp = (const float*)d_in[5];

    ssm_fused_kernel<<<NBLK, TPB>>>(x, Wb, Wc, Wd, A, dp, (float*)d_out);
}